// round 15
// baseline (speedup 1.0000x reference)
#include <cuda_runtime.h>
#include <math.h>
#include <stdint.h>

#define B_SZ   2
#define NTOK   2048
#define DIM    1024
#define NH     16
#define HD     64
#define M_TOT  (B_SZ * NTOK)      // 4096
#define QT     256                // attention query tile

// ---------------- scratch (device globals; no runtime allocation) ----------
__device__ float g_x [M_TOT * DIM];            // tf32-rounded x
__device__ float g_wq[DIM * DIM];              // tf32-rounded weights
__device__ float g_wk[DIM * DIM];
__device__ float g_wv[DIM * DIM];
__device__ float g_wp[DIM * DIM];
__device__ float g_q[B_SZ * NH * NTOK * HD];   // [B,H,N,hd] (tf32-rounded)
__device__ float g_k[B_SZ * NH * NTOK * HD];   // [B,H,N,hd]
__device__ float g_v[B_SZ * NH * HD * NTOK];   // [B,H,hd,N]  TRANSPOSED
__device__ float g_h[M_TOT * DIM];             // attention out (tf32-rounded)
__device__ float g_gate[M_TOT];                // per-token gate scalar

// ---------------- tf32 helpers --------------------------------------------
__device__ __forceinline__ uint32_t f2tf32(float x) {
    uint32_t r;
    asm("cvt.rna.tf32.f32 %0, %1;" : "=r"(r) : "f"(x));
    return r;
}
__device__ __forceinline__ float rnd32(float x) { return __uint_as_float(f2tf32(x)); }

// D(16x8) += A(16x8,row) * B(8x8,col);  tf32 in, f32 accum
__device__ __forceinline__ void mma_tf32(float* c, const uint32_t* a, const uint32_t* b) {
    asm volatile(
        "mma.sync.aligned.m16n8k8.row.col.f32.tf32.tf32.f32 "
        "{%0,%1,%2,%3}, {%4,%5,%6,%7}, {%8,%9}, {%0,%1,%2,%3};"
        : "+f"(c[0]), "+f"(c[1]), "+f"(c[2]), "+f"(c[3])
        : "r"(a[0]), "r"(a[1]), "r"(a[2]), "r"(a[3]), "r"(b[0]), "r"(b[1]));
}

#define LDSM4(r0, r1, r2, r3, addr) \
    asm volatile("ldmatrix.sync.aligned.m8n8.x4.shared.b16 {%0,%1,%2,%3}, [%4];" \
        : "=r"(r0), "=r"(r1), "=r"(r2), "=r"(r3) : "r"(addr))

__device__ __forceinline__ void cp_async16(uint32_t smem_addr, const void* gptr) {
    asm volatile("cp.async.cg.shared.global [%0], [%1], 16;"
                 :: "r"(smem_addr), "l"(gptr));
}
__device__ __forceinline__ void cp_commit() {
    asm volatile("cp.async.commit_group;");
}
__device__ __forceinline__ void cp_wait0() {
    asm volatile("cp.async.wait_group 0;");
}

// ===========================================================================
// Kernel 0: pre-convert all fp32 inputs -> tf32-rounded (one launch).
// index space: [0, NX4) = x, then 4 weight segments of NW4 each.
// ===========================================================================
#define NX4 (M_TOT * DIM / 4)     // 1,048,576
#define NW4 (DIM * DIM / 4)       // 262,144

__global__ void cvt_all(const float4* __restrict__ x,
                        const float4* __restrict__ wq, const float4* __restrict__ wk,
                        const float4* __restrict__ wv, const float4* __restrict__ wp)
{
    const int total = NX4 + 4 * NW4;
    int i = blockIdx.x * blockDim.x + threadIdx.x;
    int stride = gridDim.x * blockDim.x;
    for (; i < total; i += stride) {
        const float4* src;
        float4* dst;
        if (i < NX4) {
            src = x + i;
            dst = (float4*)g_x + i;
        } else {
            int r = i - NX4;
            int s = r >> 18;          // NW4 = 2^18
            int o = r & (NW4 - 1);
            const float4* ws = (s == 0) ? wq : (s == 1) ? wk : (s == 2) ? wv : wp;
            float4* wd = (s == 0) ? (float4*)g_wq : (s == 1) ? (float4*)g_wk
                       : (s == 2) ? (float4*)g_wv : (float4*)g_wp;
            src = ws + o;
            dst = wd + o;
        }
        float4 v = *src;
        *dst = make_float4(rnd32(v.x), rnd32(v.y), rnd32(v.z), rnd32(v.w));
    }
}

// ===========================================================================
// Kernel 1: fused QKV projection (tf32, cp.async 2-stage, ldmatrix frags).
// V segment written TRANSPOSED to g_v [B,H,hd,N].
// Block 128x128, 8 warps (64x32).  grid = (32, 24), 256 threads.
// ===========================================================================
__global__ __launch_bounds__(256, 2) void qkv_gemm(
    const float* __restrict__ bq, const float* __restrict__ bk,
    const float* __restrict__ bv)
{
    __shared__ __align__(16) uint32_t As[2][128][20];
    __shared__ __align__(16) uint32_t Bs[2][128][20];

    const int tid  = threadIdx.x;
    const int warp = tid >> 5, lane = tid & 31;
    const int g = lane >> 2, t = lane & 3;
    const int wm = (warp >> 2) * 64;
    const int wn = (warp & 3) * 32;

    const int quad = lane >> 3, r8 = lane & 7;
    const int aRow = ((quad & 1) << 3) + r8;
    const int aCol = (quad >> 1) << 2;
    const int bRow = ((quad >> 1) << 3) + r8;
    const int bCol = (quad & 1) << 2;

    const int m0 = blockIdx.x * 128;
    const int n0 = blockIdx.y * 128;
    const int seg = n0 >> 10;
    const float* W    = (seg == 0) ? g_wq : (seg == 1) ? g_wk : g_wv;
    const float* bias = (seg == 0) ? bq : (seg == 1) ? bk : bv;
    const int ncol0 = n0 & 1023;

    const int row = tid >> 1;
    const int q8  = (tid & 1) * 8;

    float acc[4][4][4];
#pragma unroll
    for (int i = 0; i < 4; i++)
#pragma unroll
        for (int j = 0; j < 4; j++)
#pragma unroll
            for (int r = 0; r < 4; r++) acc[i][j][r] = 0.f;

    const float* aPtr = g_x + (m0 + row) * DIM + q8;
    const float* bPtr = W + (ncol0 + row) * DIM + q8;
    const uint32_t sA0 = (uint32_t)__cvta_generic_to_shared(&As[0][row][q8]);
    const uint32_t sB0 = (uint32_t)__cvta_generic_to_shared(&Bs[0][row][q8]);
    const uint32_t sAb = (uint32_t)__cvta_generic_to_shared(&As[0][0][0]);
    const uint32_t sBb = (uint32_t)__cvta_generic_to_shared(&Bs[0][0][0]);
    const uint32_t stageBytes = 128 * 20 * 4;

    cp_async16(sA0,      aPtr);
    cp_async16(sA0 + 16, aPtr + 4);
    cp_async16(sB0,      bPtr);
    cp_async16(sB0 + 16, bPtr + 4);
    cp_commit();

    for (int kt = 0; kt < 64; kt++) {
        const int cur = kt & 1;
        cp_wait0();
        __syncthreads();
        if (kt < 63) {
            const uint32_t off = (cur ^ 1) * stageBytes;
            const float* ap = aPtr + (kt + 1) * 16;
            const float* bp = bPtr + (kt + 1) * 16;
            cp_async16(sA0 + off,      ap);
            cp_async16(sA0 + off + 16, ap + 4);
            cp_async16(sB0 + off,      bp);
            cp_async16(sB0 + off + 16, bp + 4);
            cp_commit();
        }

        const uint32_t sAc = sAb + cur * stageBytes;
        const uint32_t sBc = sBb + cur * stageBytes;
#pragma unroll
        for (int kk = 0; kk < 16; kk += 8) {
            uint32_t afr[4][4], bfr[4][2];
#pragma unroll
            for (int mi = 0; mi < 4; mi++)
                LDSM4(afr[mi][0], afr[mi][1], afr[mi][2], afr[mi][3],
                      sAc + (((wm + mi * 16 + aRow) * 20) + kk + aCol) * 4);
#pragma unroll
            for (int n2 = 0; n2 < 2; n2++)
                LDSM4(bfr[2 * n2][0], bfr[2 * n2][1], bfr[2 * n2 + 1][0], bfr[2 * n2 + 1][1],
                      sBc + (((wn + n2 * 16 + bRow) * 20) + kk + bCol) * 4);
#pragma unroll
            for (int mi = 0; mi < 4; mi++)
#pragma unroll
                for (int ni = 0; ni < 4; ni++)
                    mma_tf32(acc[mi][ni], afr[mi], bfr[ni]);
        }
    }

    // epilogue: bias, round to tf32, scatter.
    // Q,K -> [B,H,N,hd];  V -> TRANSPOSED [B,H,hd,N].
#pragma unroll
    for (int mi = 0; mi < 4; mi++) {
#pragma unroll
        for (int h = 0; h < 2; h++) {
            int m = m0 + wm + mi * 16 + g + 8 * h;
            int bb = m >> 11, n = m & 2047;
#pragma unroll
            for (int ni = 0; ni < 4; ni++) {
                int col = ncol0 + wn + ni * 8 + 2 * t;
                int head = col >> 6, d = col & 63;
                float v0 = rnd32(acc[mi][ni][2 * h + 0] + bias[col + 0]);
                float v1 = rnd32(acc[mi][ni][2 * h + 1] + bias[col + 1]);
                if (seg == 2) {
                    float* vb = g_v + ((bb * NH + head) * HD + d) * NTOK + n;
                    vb[0]    = v0;
                    vb[NTOK] = v1;
                } else {
                    float* ob = (seg == 0) ? g_q : g_k;
                    *(float2*)&ob[(((bb * NH + head) * NTOK) + n) * HD + d] =
                        make_float2(v0, v1);
                }
            }
        }
    }
}

// ===========================================================================
// Kernel 2: flash attention, tf32 mma, cp.async K/V double buffer,
// ldmatrix fragment loads for Q, K, P AND V (V transposed in gmem).
// grid = (8, 32), 256 threads, ~204KB dynamic smem.
// ===========================================================================
#define ATTN_SMEM ((QT * 68 * 2 + 4 * 64 * 68) * 4)

__global__ __launch_bounds__(256, 1) void attn_kernel(
    const float* __restrict__ temperature,
    const float* __restrict__ qe)
{
    extern __shared__ uint32_t smu[];
    uint32_t* Qs = smu;                       // [q][d]     stride 68, QT rows
    uint32_t* Ks = Qs + QT * 68;              // [2][key][d] stride 68
    uint32_t* Vs = Ks + 2 * 64 * 68;          // [2][d][key] stride 68 (transposed)
    uint32_t* Ps = Vs + 2 * 64 * 68;          // [q][key]   stride 68, QT rows

    const int tid  = threadIdx.x;
    const int warp = tid >> 5, lane = tid & 31;
    const int g = lane >> 2, t = lane & 3;
    const int wq = warp * 32;

    const int quad = lane >> 3, r8 = lane & 7;
    const int aRow = ((quad & 1) << 3) + r8;
    const int aCol = (quad >> 1) << 2;
    const int bRow = ((quad >> 1) << 3) + r8;
    const int bCol = (quad & 1) << 2;

    const int bh = blockIdx.y;
    const int b = bh >> 4, hh = bh & 15;
    const int q0 = blockIdx.x * QT;

    const float* qbase = g_q + (bh * NTOK + q0) * HD;
    const float* kbase = g_k + (long)bh * NTOK * HD;
    const float* vbase = g_v + (long)bh * HD * NTOK;   // [hd][N]

    const uint32_t sQ  = (uint32_t)__cvta_generic_to_shared(Qs);
    const uint32_t sKb = (uint32_t)__cvta_generic_to_shared(Ks);
    const uint32_t sVb = (uint32_t)__cvta_generic_to_shared(Vs);
    const uint32_t sP  = (uint32_t)__cvta_generic_to_shared(Ps);

    // staging: thread (j = tid>>2, c4 = tid&3); K row = key j, V row = d j
    const int j  = tid >> 2;
    const int c4 = tid & 3;
    const uint32_t sK0 = (uint32_t)__cvta_generic_to_shared(&Ks[j * 68 + c4 * 16]);
    const uint32_t sV0 = (uint32_t)__cvta_generic_to_shared(&Vs[j * 68 + c4 * 16]);
    const uint32_t stage = 64 * 68 * 4;
    const float* kp0 = kbase + j * HD + c4 * 16;          // key j, d chunk
    const float* vp0 = vbase + j * NTOK + c4 * 16;        // d j, key chunk

#pragma unroll
    for (int f = 0; f < 4; f++) {
        cp_async16(sK0 + f * 16, kp0 + f * 4);
        cp_async16(sV0 + f * 16, vp0 + f * 4);
    }
    cp_commit();

    // ---- Q preprocess (overlaps K/V load): one row per thread
    {
        int r = tid;
        float qv[64];
        float ss = 0.f;
#pragma unroll
        for (int f = 0; f < 16; f++) {
            float4 v = *(const float4*)(qbase + r * HD + f * 4);
            qv[f * 4 + 0] = v.x; qv[f * 4 + 1] = v.y;
            qv[f * 4 + 2] = v.z; qv[f * 4 + 3] = v.w;
            ss += v.x * v.x + v.y * v.y + v.z * v.z + v.w * v.w;
        }
        float inv = rsqrtf(ss);
        float tt = temperature[hh];
        float sp = (tt > 20.f) ? tt : log1pf(__expf(tt));
        float tc = sp * 0.125f;                      // /sqrt(64)
        const float* qeh = qe + hh * HD;
#pragma unroll
        for (int f = 0; f < 16; f++) {
            uint4 u;
            u.x = f2tf32((qv[f * 4 + 0] * inv + qeh[f * 4 + 0]) * tc);
            u.y = f2tf32((qv[f * 4 + 1] * inv + qeh[f * 4 + 1]) * tc);
            u.z = f2tf32((qv[f * 4 + 2] * inv + qeh[f * 4 + 2]) * tc);
            u.w = f2tf32((qv[f * 4 + 3] * inv + qeh[f * 4 + 3]) * tc);
            *(uint4*)&Qs[r * 68 + f * 4] = u;
        }
    }

    float oacc[2][8][4];
    float mi[2][2], li[2][2];
#pragma unroll
    for (int m = 0; m < 2; m++) {
#pragma unroll
        for (int i = 0; i < 8; i++)
#pragma unroll
            for (int r = 0; r < 4; r++) oacc[m][i][r] = 0.f;
        mi[m][0] = mi[m][1] = -1e30f;
        li[m][0] = li[m][1] = 0.f;
    }

    for (int kt = 0; kt < NTOK / 64; kt++) {
        const int cur = kt & 1;
        const uint32_t sKc = sKb + cur * stage;
        const uint32_t sVc = sVb + cur * stage;

        cp_wait0();
        __syncthreads();

        if (kt < NTOK / 64 - 1) {
            const uint32_t off = (cur ^ 1) * stage;
            const float* kp = kp0 + (kt + 1) * 64 * HD;   // keys advance rows
            const float* vp = vp0 + (kt + 1) * 64;        // keys advance cols
#pragma unroll
            for (int f = 0; f < 4; f++) {
                cp_async16(sK0 + off + f * 16, kp + f * 4);
                cp_async16(sV0 + off + f * 16, vp + f * 4);
            }
            cp_commit();
        }

        // ---- S = Q K^T : warp tile 32(q) x 64(key)
        float sacc[2][8][4];
#pragma unroll
        for (int m = 0; m < 2; m++)
#pragma unroll
            for (int i = 0; i < 8; i++)
#pragma unroll
                for (int r = 0; r < 4; r++) sacc[m][i][r] = 0.f;

#pragma unroll
        for (int kk = 0; kk < 64; kk += 8) {
            uint32_t afr[2][4], bfr[8][2];
#pragma unroll
            for (int m = 0; m < 2; m++)
                LDSM4(afr[m][0], afr[m][1], afr[m][2], afr[m][3],
                      sQ + (((wq + m * 16 + aRow) * 68) + kk + aCol) * 4);
#pragma unroll
            for (int n2 = 0; n2 < 4; n2++)
                LDSM4(bfr[2 * n2][0], bfr[2 * n2][1], bfr[2 * n2 + 1][0], bfr[2 * n2 + 1][1],
                      sKc + (((n2 * 16 + bRow) * 68) + kk + bCol) * 4);
#pragma unroll
            for (int m = 0; m < 2; m++)
#pragma unroll
                for (int ni = 0; ni < 8; ni++)
                    mma_tf32(sacc[m][ni], afr[m], bfr[ni]);
        }

        // ---- online softmax, warp-local
#pragma unroll
        for (int m = 0; m < 2; m++) {
#pragma unroll
            for (int i = 0; i < 2; i++) {
                int idx = 2 * i;
                float rm = -1e30f;
#pragma unroll
                for (int ni = 0; ni < 8; ni++)
                    rm = fmaxf(rm, fmaxf(sacc[m][ni][idx], sacc[m][ni][idx + 1]));
                rm = fmaxf(rm, __shfl_xor_sync(0xffffffffu, rm, 1));
                rm = fmaxf(rm, __shfl_xor_sync(0xffffffffu, rm, 2));
                float mnew = fmaxf(mi[m][i], rm);
                float corr = __expf(mi[m][i] - mnew);
                float rs = 0.f;
#pragma unroll
                for (int ni = 0; ni < 8; ni++) {
                    float p0 = __expf(sacc[m][ni][idx]     - mnew);
                    float p1 = __expf(sacc[m][ni][idx + 1] - mnew);
                    rs += p0 + p1;
                    *(uint2*)&Ps[(wq + m * 16 + g + 8 * i) * 68 + ni * 8 + 2 * t] =
                        make_uint2(f2tf32(p0), f2tf32(p1));
                }
                rs += __shfl_xor_sync(0xffffffffu, rs, 1);
                rs += __shfl_xor_sync(0xffffffffu, rs, 2);
                li[m][i] = li[m][i] * corr + rs;
                mi[m][i] = mnew;
#pragma unroll
                for (int ni = 0; ni < 8; ni++) {
                    oacc[m][ni][idx]     *= corr;
                    oacc[m][ni][idx + 1] *= corr;
                }
            }
        }
        __syncwarp();                    // Ps writes -> ldmatrix reads (warp-private)

        // ---- O += P V : warp tile 32(q) x 64(d), V via ldmatrix (transposed)
#pragma unroll
        for (int kk = 0; kk < 64; kk += 8) {
            uint32_t afr[2][4], bfr[8][2];
#pragma unroll
            for (int m = 0; m < 2; m++)
                LDSM4(afr[m][0], afr[m][1], afr[m][2], afr[m][3],
                      sP + (((wq + m * 16 + aRow) * 68) + kk + aCol) * 4);
#pragma unroll
            for (int n2 = 0; n2 < 4; n2++)
                LDSM4(bfr[2 * n2][0], bfr[2 * n2][1], bfr[2 * n2 + 1][0], bfr[2 * n2 + 1][1],
                      sVc + (((n2 * 16 + bRow) * 68) + kk + bCol) * 4);
#pragma unroll
            for (int m = 0; m < 2; m++)
#pragma unroll
                for (int ni = 0; ni < 8; ni++)
                    mma_tf32(oacc[m][ni], afr[m], bfr[ni]);
        }
        __syncwarp();
    }

    // ---- epilogue: /l, round to tf32 (consumed by tf32 proj), write h
#pragma unroll
    for (int m = 0; m < 2; m++) {
#pragma unroll
        for (int i = 0; i < 2; i++) {
            int idx = 2 * i;
            float invl = 1.0f / li[m][i];
            int n = q0 + wq + m * 16 + g + 8 * i;
#pragma unroll
            for (int ni = 0; ni < 8; ni++) {
                int col = ni * 8 + 2 * t;
                float2 vo;
                vo.x = rnd32(oacc[m][ni][idx]     * invl);
                vo.y = rnd32(oacc[m][ni][idx + 1] * invl);
                *(float2*)&g_h[(b * NTOK + n) * DIM + hh * HD + col] = vo;
            }
        }
    }
}

// ===========================================================================
// Kernel 3: gating -> scalar g per token (fp32, one warp per token).
// ===========================================================================
__global__ __launch_bounds__(256) void gate_kernel(
    const float* __restrict__ Wr, const float* __restrict__ br,
    const float* __restrict__ Ws, const float* __restrict__ bs)
{
    const int warp = threadIdx.x >> 5, lane = threadIdx.x & 31;
    const int tok = blockIdx.x * 8 + warp;
    const float* hrow = g_h + tok * DIM;

    float hv[32];
#pragma unroll
    for (int kk = 0; kk < 32; kk++) hv[kk] = hrow[lane + 32 * kk];

    float myLogit = -1e30f;
#pragma unroll
    for (int wi = 0; wi < 17; wi++) {
        const float* wrow = (wi < 15) ? (Wr + wi * DIM) : (Ws + (wi - 15) * DIM);
        float sum = 0.f;
#pragma unroll
        for (int kk = 0; kk < 32; kk++) sum += hv[kk] * wrow[lane + 32 * kk];
#pragma unroll
        for (int off = 16; off; off >>= 1) sum += __shfl_xor_sync(0xffffffffu, sum, off);
        float bias = (wi < 15) ? br[wi] : bs[wi - 15];
        if (lane == wi) myLogit = sum + bias;
    }

    float v15 = (lane < 15) ? myLogit : -1e30f;
    float m15 = v15;
#pragma unroll
    for (int off = 16; off; off >>= 1) m15 = fmaxf(m15, __shfl_xor_sync(0xffffffffu, m15, off));
    float e = (lane < 15) ? __expf(myLogit - m15) : 0.f;
    float ssum = e;
#pragma unroll
    for (int off = 16; off; off >>= 1) ssum += __shfl_xor_sync(0xffffffffu, ssum, off);
    float inv = 1.f / ssum;

    float vv = e;
    float gsum3 = 0.f;
    for (int pick = 0; pick < 3; pick++) {
        float pm = vv;
#pragma unroll
        for (int off = 16; off; off >>= 1) pm = fmaxf(pm, __shfl_xor_sync(0xffffffffu, pm, off));
        gsum3 += pm;
        unsigned eqm = __ballot_sync(0xffffffffu, vv == pm);
        int first = __ffs(eqm) - 1;
        if (lane == first) vv = -1.f;
    }
    gsum3 *= inv;

    float l15 = __shfl_sync(0xffffffffu, myLogit, 15);
    float l16 = __shfl_sync(0xffffffffu, myLogit, 16);
    float m2 = fmaxf(l15, l16);
    float e0 = __expf(l15 - m2), e1 = __expf(l16 - m2);
    float s2 = e0 + e1;
    float s0 = e0 / s2, s1 = e1 / s2;

    if (lane == 0)
        g_gate[tok] = 2.f * s0 * (s0 + s1) + 6.f * s1 * gsum3;
}

// ===========================================================================
// Kernel 4: output projection (tf32, cp.async, ldmatrix frags).
// out = g .* (h @ Wp^T) + bp.  grid = (32, 8), 256 threads.
// ===========================================================================
__global__ __launch_bounds__(256, 2) void proj_gemm(
    const float* __restrict__ bp, float* __restrict__ out)
{
    __shared__ __align__(16) uint32_t As[2][128][20];
    __shared__ __align__(16) uint32_t Bs[2][128][20];

    const int tid  = threadIdx.x;
    const int warp = tid >> 5, lane = tid & 31;
    const int g = lane >> 2, t = lane & 3;
    const int wm = (warp >> 2) * 64;
    const int wn = (warp & 3) * 32;

    const int quad = lane >> 3, r8 = lane & 7;
    const int aRow = ((quad & 1) << 3) + r8;
    const int aCol = (quad >> 1) << 2;
    const int bRow = ((quad >> 1) << 3) + r8;
    const int bCol = (quad & 1) << 2;

    const int m0 = blockIdx.x * 128;
    const int n0 = blockIdx.y * 128;
    const int row = tid >> 1;
    const int q8  = (tid & 1) * 8;

    float acc[4][4][4];
#pragma unroll
    for (int i = 0; i < 4; i++)
#pragma unroll
        for (int j = 0; j < 4; j++)
#pragma unroll
            for (int r = 0; r < 4; r++) acc[i][j][r] = 0.f;

    const float* aPtr = g_h + (m0 + row) * DIM + q8;
    const float* bPtr = g_wp + (n0 + row) * DIM + q8;
    const uint32_t sA0 = (uint32_t)__cvta_generic_to_shared(&As[0][row][q8]);
    const uint32_t sB0 = (uint32_t)__cvta_generic_to_shared(&Bs[0][row][q8]);
    const uint32_t sAb = (uint32_t)__cvta_generic_to_shared(&As[0][0][0]);
    const uint32_t sBb = (uint32_t)__cvta_generic_to_shared(&Bs[0][0][0]);
    const uint32_t stageBytes = 128 * 20 * 4;

    cp_async16(sA0,      aPtr);
    cp_async16(sA0 + 16, aPtr + 4);
    cp_async16(sB0,      bPtr);
    cp_async16(sB0 + 16, bPtr + 4);
    cp_commit();

    for (int kt = 0; kt < 64; kt++) {
        const int cur = kt & 1;
        cp_wait0();
        __syncthreads();
        if (kt < 63) {
            const uint32_t off = (cur ^ 1) * stageBytes;
            const float* ap = aPtr + (kt + 1) * 16;
            const float* bp2 = bPtr + (kt + 1) * 16;
            cp_async16(sA0 + off,      ap);
            cp_async16(sA0 + off + 16, ap + 4);
            cp_async16(sB0 + off,      bp2);
            cp_async16(sB0 + off + 16, bp2 + 4);
            cp_commit();
        }

        const uint32_t sAc = sAb + cur * stageBytes;
        const uint32_t sBc = sBb + cur * stageBytes;
#pragma unroll
        for (int kk = 0; kk < 16; kk += 8) {
            uint32_t afr[4][4], bfr[4][2];
#pragma unroll
            for (int mi = 0; mi < 4; mi++)
                LDSM4(afr[mi][0], afr[mi][1], afr[mi][2], afr[mi][3],
                      sAc + (((wm + mi * 16 + aRow) * 20) + kk + aCol) * 4);
#pragma unroll
            for (int n2 = 0; n2 < 2; n2++)
                LDSM4(bfr[2 * n2][0], bfr[2 * n2][1], bfr[2 * n2 + 1][0], bfr[2 * n2 + 1][1],
                      sBc + (((wn + n2 * 16 + bRow) * 20) + kk + bCol) * 4);
#pragma unroll
            for (int mi = 0; mi < 4; mi++)
#pragma unroll
                for (int ni = 0; ni < 4; ni++)
                    mma_tf32(acc[mi][ni], afr[mi], bfr[ni]);
        }
    }

    // epilogue: apply row gate, add bias
#pragma unroll
    for (int mi = 0; mi < 4; mi++) {
#pragma unroll
        for (int h = 0; h < 2; h++) {
            int m = m0 + wm + mi * 16 + g + 8 * h;
            float gm = g_gate[m];
#pragma unroll
            for (int ni = 0; ni < 4; ni++) {
                int col = n0 + wn + ni * 8 + 2 * t;
                float2 vo;
                vo.x = gm * acc[mi][ni][2 * h + 0] + bp[col + 0];
                vo.y = gm * acc[mi][ni][2 * h + 1] + bp[col + 1];
                *(float2*)&out[m * DIM + col] = vo;
            }
        }
    }
}

// ===========================================================================
extern "C" void kernel_launch(void* const* d_in, const int* in_sizes, int n_in,
                              void* d_out, int out_size)
{
    const float* x  = (const float*)d_in[0];
    const float* Wq = (const float*)d_in[1];
    const float* bq = (const float*)d_in[2];
    const float* Wk = (const float*)d_in[3];
    const float* bk = (const float*)d_in[4];
    const float* Wv = (const float*)d_in[5];
    const float* bv = (const float*)d_in[6];
    const float* Wp = (const float*)d_in[7];
    const float* bp = (const float*)d_in[8];
    const float* Wr = (const float*)d_in[9];
    const float* br = (const float*)d_in[10];
    const float* Ws = (const float*)d_in[11];
    const float* bs = (const float*)d_in[12];
    const float* tp = (const float*)d_in[13];
    const float* qe = (const float*)d_in[14];
    float* out = (float*)d_out;

    cudaFuncSetAttribute(attn_kernel,
                         cudaFuncAttributeMaxDynamicSharedMemorySize, ATTN_SMEM);

    cvt_all<<<2048, 256>>>((const float4*)x,
                           (const float4*)Wq, (const float4*)Wk,
                           (const float4*)Wv, (const float4*)Wp);

    qkv_gemm<<<dim3(32, 24), 256>>>(bq, bk, bv);
    attn_kernel<<<dim3(8, 32), 256, ATTN_SMEM>>>(tp, qe);
    gate_kernel<<<512, 256>>>(Wr, br, Ws, bs);
    proj_gemm<<<dim3(32, 8), 256>>>(bp, out);
}